// round 3
// baseline (speedup 1.0000x reference)
#include <cuda_runtime.h>
#include <mma.h>
#include <math.h>
#include <stdint.h>

using namespace nvcuda;

// ---------------- problem constants ----------------
#define T_TOK 4096
#define HIDN  2048
#define NH    16
#define NKV   4
#define HD    128
#define FF    8192
#define BATCH 4
#define SEQ   1024
#define GRP   (NH / NKV)
#define KVW   (NKV * HD)          // 512
#define EPSV  1e-6f
#define SCALE 0.08838834764831845f

// ---------------- scratch ----------------
#define OFF_H      ((size_t)0)
#define OFF_Q      ((size_t)8388608)
#define OFF_K      ((size_t)16777216)
#define OFF_V      ((size_t)18874368)
#define OFF_SCORES ((size_t)20971520)
#define OFF_ATTN   ((size_t)88080384)
#define OFF_X2     ((size_t)96468992)
#define OFF_GATE   ((size_t)104857600)
#define OFF_UP     ((size_t)138412032)
#define SCRATCH_FLOATS ((size_t)171966464)

__device__ float g_scratch[SCRATCH_FLOATS];

// ---------------- GEMM config ----------------
#define BM 128
#define BN 128
#define BK 32
#define PITCH 36                   // 32 + 4 pad (floats)
#define ASTAGE (128 * PITCH)       // floats per A stage
#define BPITCH_NN 132              // PV: [BK][BN] layout
#define BSTAGE_NN (BK * BPITCH_NN)

#define SMEM_TN_BYTES (3 * (ASTAGE + ASTAGE) * 4)            // 110592
#define SMEM_PV_BYTES (3 * (ASTAGE + BSTAGE_NN) * 4)         // 105984

__device__ __forceinline__ float tf32r(float x) { return wmma::__float_to_tf32(x); }

__device__ __forceinline__ void cp16(uint32_t dst, const float* src) {
    asm volatile("cp.async.cg.shared.global [%0], [%1], 16;" :: "r"(dst), "l"(src));
}
__device__ __forceinline__ void cp_commit() {
    asm volatile("cp.async.commit_group;");
}
template <int N>
__device__ __forceinline__ void cp_wait() {
    asm volatile("cp.async.wait_group %0;" :: "n"(N));
}

// fragment types
typedef wmma::fragment<wmma::matrix_a, 16, 16, 8, wmma::precision::tf32, wmma::row_major> AFrag;
typedef wmma::fragment<wmma::matrix_b, 16, 16, 8, wmma::precision::tf32, wmma::col_major> BFragCol;
typedef wmma::fragment<wmma::matrix_b, 16, 16, 8, wmma::precision::tf32, wmma::row_major> BFragRow;
typedef wmma::fragment<wmma::accumulator, 16, 16, 8, float> CFrag;

#define CVT_FRAG(f) _Pragma("unroll") for (int _e = 0; _e < (f).num_elements; _e++) (f).x[_e] = tf32r((f).x[_e]);

// ============================================================
// TN GEMM: C[M,N] = A[M,K] @ B[N,K]^T  (+epilogue)
// EPI: 0 none, 1 +bias[n], 2 +res
// ============================================================
template <int EPI>
__global__ void __launch_bounds__(256, 2)
cgemm_tn(const float* __restrict__ A, int lda,
         const float* __restrict__ B, int ldb,
         float* __restrict__ C, int ldc, int K,
         const float* __restrict__ bias,
         const float* __restrict__ res)
{
    extern __shared__ float smem[];
    float* SA = smem;
    float* SB = smem + 3 * ASTAGE;

    const int tid  = threadIdx.x;
    const int wid  = tid >> 5;
    const int lane = tid & 31;
    const int m0 = blockIdx.y * BM;
    const int n0 = blockIdx.x * BN;
    const int wm = wid & 1, wn = wid >> 1;

    CFrag c[4][2];
#pragma unroll
    for (int i = 0; i < 4; i++)
#pragma unroll
        for (int j = 0; j < 2; j++) wmma::fill_fragment(c[i][j], 0.f);

    const int row  = tid >> 1;          // 0..127
    const int coff = (tid & 1) << 4;    // 0 or 16
    const float* gA = A + (size_t)(m0 + row) * lda + coff;
    const float* gB = B + (size_t)(n0 + row) * ldb + coff;
    const uint32_t da = (uint32_t)__cvta_generic_to_shared(SA) + (uint32_t)(row * PITCH + coff) * 4u;
    const uint32_t db = (uint32_t)__cvta_generic_to_shared(SB) + (uint32_t)(row * PITCH + coff) * 4u;

    const int nt = K / BK;

#define LOAD_STAGE_TN(s, k0) do {                                     \
        uint32_t _o = (uint32_t)(s) * (ASTAGE * 4u);                  \
        _Pragma("unroll")                                             \
        for (int _j = 0; _j < 4; _j++) {                              \
            cp16(da + _o + _j * 16u, gA + (k0) + _j * 4);             \
            cp16(db + _o + _j * 16u, gB + (k0) + _j * 4);             \
        }                                                             \
    } while (0)

    LOAD_STAGE_TN(0, 0); cp_commit();
    LOAD_STAGE_TN(1, BK); cp_commit();

    for (int t = 0; t < nt; t++) {
        cp_wait<1>();
        __syncthreads();
        if (t + 2 < nt) { int s = (t + 2) % 3; LOAD_STAGE_TN(s, (t + 2) * BK); }
        cp_commit();

        const float* sa = SA + (t % 3) * ASTAGE;
        const float* sb = SB + (t % 3) * ASTAGE;
#pragma unroll
        for (int ks = 0; ks < BK; ks += 8) {
            AFrag af[4];
            BFragCol bf[2];
#pragma unroll
            for (int i = 0; i < 4; i++) {
                wmma::load_matrix_sync(af[i], sa + (wm * 64 + i * 16) * PITCH + ks, PITCH);
                CVT_FRAG(af[i]);
            }
#pragma unroll
            for (int j = 0; j < 2; j++) {
                wmma::load_matrix_sync(bf[j], sb + (wn * 32 + j * 16) * PITCH + ks, PITCH);
                CVT_FRAG(bf[j]);
            }
#pragma unroll
            for (int i = 0; i < 4; i++)
#pragma unroll
                for (int j = 0; j < 2; j++)
                    wmma::mma_sync(c[i][j], af[i], bf[j], c[i][j]);
        }
    }
    __syncthreads();

    float* stage = smem + wid * 256;
    const int r  = lane >> 1;
    const int cq = (lane & 1) << 3;
#pragma unroll
    for (int i = 0; i < 4; i++) {
#pragma unroll
        for (int j = 0; j < 2; j++) {
            wmma::store_matrix_sync(stage, c[i][j], 16, wmma::mem_row_major);
            __syncwarp();
            const size_t row_g = (size_t)(m0 + wm * 64 + i * 16 + r);
            const size_t col_g = (size_t)(n0 + wn * 32 + j * 16 + cq);
            float4 v0 = *(float4*)&stage[r * 16 + cq];
            float4 v1 = *(float4*)&stage[r * 16 + cq + 4];
            if (EPI == 1) {
                float4 b0 = *(const float4*)&bias[col_g];
                float4 b1 = *(const float4*)&bias[col_g + 4];
                v0.x += b0.x; v0.y += b0.y; v0.z += b0.z; v0.w += b0.w;
                v1.x += b1.x; v1.y += b1.y; v1.z += b1.z; v1.w += b1.w;
            }
            if (EPI == 2) {
                float4 r0 = *(const float4*)&res[row_g * ldc + col_g];
                float4 r1 = *(const float4*)&res[row_g * ldc + col_g + 4];
                v0.x += r0.x; v0.y += r0.y; v0.z += r0.z; v0.w += r0.w;
                v1.x += r1.x; v1.y += r1.y; v1.z += r1.z; v1.w += r1.w;
            }
            *(float4*)&C[row_g * ldc + col_g] = v0;
            *(float4*)&C[row_g * ldc + col_g + 4] = v1;
            __syncwarp();
        }
    }
#undef LOAD_STAGE_TN
}

// ============================================================
// Scores: scores[z,s,t] = (q.k)*SCALE + mask ; skip upper blocks
// ============================================================
__global__ void __launch_bounds__(256, 2)
cscores(const float* __restrict__ q, const float* __restrict__ k,
        const float* __restrict__ mask, float* __restrict__ scores)
{
    if (blockIdx.x > blockIdx.y) return;   // fully masked: never read downstream

    const int z = blockIdx.z;
    const int b = z / NH, h = z % NH, kvh = h / GRP;
    const int m0 = blockIdx.y * BM;
    const int n0 = blockIdx.x * BN;
    const float* A = q + (size_t)b * SEQ * HIDN + (size_t)h * HD;
    const float* B = k + (size_t)b * SEQ * KVW + (size_t)kvh * HD;
    const float* M = mask + (size_t)b * SEQ * SEQ;
    float* C = scores + (size_t)z * SEQ * SEQ;

    extern __shared__ float smem[];
    float* SA = smem;
    float* SB = smem + 3 * ASTAGE;

    const int tid  = threadIdx.x;
    const int wid  = tid >> 5;
    const int lane = tid & 31;
    const int wm = wid & 1, wn = wid >> 1;

    CFrag c[4][2];
#pragma unroll
    for (int i = 0; i < 4; i++)
#pragma unroll
        for (int j = 0; j < 2; j++) wmma::fill_fragment(c[i][j], 0.f);

    const int row  = tid >> 1;
    const int coff = (tid & 1) << 4;
    const float* gA = A + (size_t)(m0 + row) * HIDN + coff;
    const float* gB = B + (size_t)(n0 + row) * KVW + coff;
    const uint32_t da = (uint32_t)__cvta_generic_to_shared(SA) + (uint32_t)(row * PITCH + coff) * 4u;
    const uint32_t db = (uint32_t)__cvta_generic_to_shared(SB) + (uint32_t)(row * PITCH + coff) * 4u;

#define LOAD_STAGE_S(s, k0) do {                                      \
        uint32_t _o = (uint32_t)(s) * (ASTAGE * 4u);                  \
        _Pragma("unroll")                                             \
        for (int _j = 0; _j < 4; _j++) {                              \
            cp16(da + _o + _j * 16u, gA + (k0) + _j * 4);             \
            cp16(db + _o + _j * 16u, gB + (k0) + _j * 4);             \
        }                                                             \
    } while (0)

    const int nt = HD / BK;   // 4
    LOAD_STAGE_S(0, 0); cp_commit();
    LOAD_STAGE_S(1, BK); cp_commit();

    for (int t = 0; t < nt; t++) {
        cp_wait<1>();
        __syncthreads();
        if (t + 2 < nt) { int s = (t + 2) % 3; LOAD_STAGE_S(s, (t + 2) * BK); }
        cp_commit();

        const float* sa = SA + (t % 3) * ASTAGE;
        const float* sb = SB + (t % 3) * ASTAGE;
#pragma unroll
        for (int ks = 0; ks < BK; ks += 8) {
            AFrag af[4];
            BFragCol bf[2];
#pragma unroll
            for (int i = 0; i < 4; i++) {
                wmma::load_matrix_sync(af[i], sa + (wm * 64 + i * 16) * PITCH + ks, PITCH);
                CVT_FRAG(af[i]);
            }
#pragma unroll
            for (int j = 0; j < 2; j++) {
                wmma::load_matrix_sync(bf[j], sb + (wn * 32 + j * 16) * PITCH + ks, PITCH);
                CVT_FRAG(bf[j]);
            }
#pragma unroll
            for (int i = 0; i < 4; i++)
#pragma unroll
                for (int j = 0; j < 2; j++)
                    wmma::mma_sync(c[i][j], af[i], bf[j], c[i][j]);
        }
    }
    __syncthreads();

    float* stage = smem + wid * 256;
    const int r  = lane >> 1;
    const int cq = (lane & 1) << 3;
#pragma unroll
    for (int i = 0; i < 4; i++) {
#pragma unroll
        for (int j = 0; j < 2; j++) {
            wmma::store_matrix_sync(stage, c[i][j], 16, wmma::mem_row_major);
            __syncwarp();
            const size_t row_g = (size_t)(m0 + wm * 64 + i * 16 + r);
            const size_t col_g = (size_t)(n0 + wn * 32 + j * 16 + cq);
            float4 v0 = *(float4*)&stage[r * 16 + cq];
            float4 v1 = *(float4*)&stage[r * 16 + cq + 4];
            float4 m0v = *(const float4*)&M[row_g * SEQ + col_g];
            float4 m1v = *(const float4*)&M[row_g * SEQ + col_g + 4];
            v0.x = v0.x * SCALE + m0v.x; v0.y = v0.y * SCALE + m0v.y;
            v0.z = v0.z * SCALE + m0v.z; v0.w = v0.w * SCALE + m0v.w;
            v1.x = v1.x * SCALE + m1v.x; v1.y = v1.y * SCALE + m1v.y;
            v1.z = v1.z * SCALE + m1v.z; v1.w = v1.w * SCALE + m1v.w;
            *(float4*)&C[row_g * SEQ + col_g] = v0;
            *(float4*)&C[row_g * SEQ + col_g + 4] = v1;
            __syncwarp();
        }
    }
#undef LOAD_STAGE_S
}

// ============================================================
// PV (NN): attn[b,s,h,:] = sum_{t<L} p[z,s,t] * v[b,t,kvh,:]
// causal: K-loop runs only to m0+128.
// ============================================================
__global__ void __launch_bounds__(256, 2)
cpv(const float* __restrict__ p, const float* __restrict__ v,
    float* __restrict__ out)
{
    const int z = blockIdx.z;
    const int b = z / NH, h = z % NH, kvh = h / GRP;
    const int m0 = blockIdx.y * BM;
    const float* A = p + (size_t)z * SEQ * SEQ;
    const float* B = v + (size_t)b * SEQ * KVW + (size_t)kvh * HD;
    float* C = out + (size_t)b * SEQ * HIDN + (size_t)h * HD;

    extern __shared__ float smem[];
    float* SA = smem;
    float* SB = smem + 3 * ASTAGE;

    const int tid  = threadIdx.x;
    const int wid  = tid >> 5;
    const int lane = tid & 31;
    const int wm = wid & 1, wn = wid >> 1;

    CFrag c[4][2];
#pragma unroll
    for (int i = 0; i < 4; i++)
#pragma unroll
        for (int j = 0; j < 2; j++) wmma::fill_fragment(c[i][j], 0.f);

    const int row  = tid >> 1;
    const int coff = (tid & 1) << 4;
    const int brow = tid >> 3;          // 0..31
    const int bcol = (tid & 7) << 4;    // 0..112
    const float* gA = A + (size_t)(m0 + row) * SEQ + coff;
    const uint32_t da = (uint32_t)__cvta_generic_to_shared(SA) + (uint32_t)(row * PITCH + coff) * 4u;
    const uint32_t db = (uint32_t)__cvta_generic_to_shared(SB) + (uint32_t)(brow * BPITCH_NN + bcol) * 4u;

#define LOAD_STAGE_PV(s, k0) do {                                         \
        uint32_t _oa = (uint32_t)(s) * (ASTAGE * 4u);                     \
        uint32_t _ob = (uint32_t)(s) * (BSTAGE_NN * 4u);                  \
        const float* _gb = B + (size_t)((k0) + brow) * KVW + bcol;        \
        _Pragma("unroll")                                                 \
        for (int _j = 0; _j < 4; _j++) {                                  \
            cp16(da + _oa + _j * 16u, gA + (k0) + _j * 4);                \
            cp16(db + _ob + _j * 16u, _gb + _j * 4);                      \
        }                                                                 \
    } while (0)

    const int nt = m0 / BK + 4;   // causal length (m0+128)/32
    LOAD_STAGE_PV(0, 0); cp_commit();
    LOAD_STAGE_PV(1, BK); cp_commit();

    for (int t = 0; t < nt; t++) {
        cp_wait<1>();
        __syncthreads();
        if (t + 2 < nt) { int s = (t + 2) % 3; LOAD_STAGE_PV(s, (t + 2) * BK); }
        cp_commit();

        const float* sa = SA + (t % 3) * ASTAGE;
        const float* sb = SB + (t % 3) * BSTAGE_NN;
#pragma unroll
        for (int ks = 0; ks < BK; ks += 8) {
            AFrag af[4];
            BFragRow bf[2];
#pragma unroll
            for (int i = 0; i < 4; i++) {
                wmma::load_matrix_sync(af[i], sa + (wm * 64 + i * 16) * PITCH + ks, PITCH);
                CVT_FRAG(af[i]);
            }
#pragma unroll
            for (int j = 0; j < 2; j++) {
                wmma::load_matrix_sync(bf[j], sb + ks * BPITCH_NN + (wn * 32 + j * 16), BPITCH_NN);
                CVT_FRAG(bf[j]);
            }
#pragma unroll
            for (int i = 0; i < 4; i++)
#pragma unroll
                for (int j = 0; j < 2; j++)
                    wmma::mma_sync(c[i][j], af[i], bf[j], c[i][j]);
        }
    }
    __syncthreads();

    float* stage = smem + wid * 256;
    const int r  = lane >> 1;
    const int cq = (lane & 1) << 3;
#pragma unroll
    for (int i = 0; i < 4; i++) {
#pragma unroll
        for (int j = 0; j < 2; j++) {
            wmma::store_matrix_sync(stage, c[i][j], 16, wmma::mem_row_major);
            __syncwarp();
            const size_t row_g = (size_t)(m0 + wm * 64 + i * 16 + r);
            const size_t col_g = (size_t)(wn * 32 + j * 16 + cq);
            float4 v0 = *(float4*)&stage[r * 16 + cq];
            float4 v1 = *(float4*)&stage[r * 16 + cq + 4];
            *(float4*)&C[row_g * HIDN + col_g] = v0;
            *(float4*)&C[row_g * HIDN + col_g + 4] = v1;
            __syncwarp();
        }
    }
#undef LOAD_STAGE_PV
}

// ---------------- elementwise / reduction kernels ----------------

// length-aware causal softmax: row s uses only t < L = (floor(s/128)+1)*128
__global__ void __launch_bounds__(256)
softmax_kernel(float* __restrict__ s)
{
    const size_t base = (size_t)blockIdx.x * SEQ;
    const int r = blockIdx.x & (SEQ - 1);
    const int L = ((r >> 7) + 1) << 7;
    const int tid = threadIdx.x;
    __shared__ float red[8];

    float vals[4];
    float mx = -1e30f;
    int cnt = 0;
    for (int idx = tid; idx < L; idx += 256) {
        vals[cnt] = s[base + idx];
        mx = fmaxf(mx, vals[cnt]);
        cnt++;
    }
#pragma unroll
    for (int o = 16; o > 0; o >>= 1) mx = fmaxf(mx, __shfl_xor_sync(0xffffffffu, mx, o));
    if ((tid & 31) == 0) red[tid >> 5] = mx;
    __syncthreads();
    float m2 = fmaxf(fmaxf(fmaxf(red[0], red[1]), fmaxf(red[2], red[3])),
                     fmaxf(fmaxf(red[4], red[5]), fmaxf(red[6], red[7])));
    __syncthreads();

    float sum = 0.f;
    for (int c = 0; c < cnt; c++) {
        vals[c] = expf(vals[c] - m2);
        sum += vals[c];
    }
#pragma unroll
    for (int o = 16; o > 0; o >>= 1) sum += __shfl_xor_sync(0xffffffffu, sum, o);
    if ((tid & 31) == 0) red[tid >> 5] = sum;
    __syncthreads();
    float tot = red[0] + red[1] + red[2] + red[3] + red[4] + red[5] + red[6] + red[7];
    float inv = 1.f / tot;
    int c = 0;
    for (int idx = tid; idx < L; idx += 256, c++) s[base + idx] = vals[c] * inv;
}

__global__ void __launch_bounds__(256)
rmsnorm_kernel(const float* __restrict__ x, const float* __restrict__ w,
               float* __restrict__ out)
{
    const size_t base = (size_t)blockIdx.x * HIDN;
    const int tid = threadIdx.x;
    __shared__ float red[8];

    float v[8];
    float ss = 0.f;
#pragma unroll
    for (int j = 0; j < 8; j++) {
        v[j] = x[base + tid + j * 256];
        ss += v[j] * v[j];
    }
#pragma unroll
    for (int o = 16; o > 0; o >>= 1) ss += __shfl_xor_sync(0xffffffffu, ss, o);
    if ((tid & 31) == 0) red[tid >> 5] = ss;
    __syncthreads();
    float tot = red[0] + red[1] + red[2] + red[3] + red[4] + red[5] + red[6] + red[7];
    float r = rsqrtf(tot * (1.f / HIDN) + EPSV);
#pragma unroll
    for (int j = 0; j < 8; j++)
        out[base + tid + j * 256] = v[j] * r * w[tid + j * 256];
}

__global__ void __launch_bounds__(128)
head_rms_rope_kernel(float* __restrict__ buf, const float* __restrict__ w,
                     const float* __restrict__ cs, const float* __restrict__ sn,
                     int nheads)
{
    const int t = blockIdx.x;
    const int h = blockIdx.y;
    const int i = threadIdx.x;
    const size_t idx = (size_t)t * nheads * HD + (size_t)h * HD + i;

    float v = buf[idx];
    float ss = v * v;
#pragma unroll
    for (int o = 16; o > 0; o >>= 1) ss += __shfl_xor_sync(0xffffffffu, ss, o);
    __shared__ float red[4];
    if ((i & 31) == 0) red[i >> 5] = ss;
    __syncthreads();
    float tot = red[0] + red[1] + red[2] + red[3];
    float n = v * rsqrtf(tot * (1.f / HD) + EPSV) * w[i];

    __shared__ float sm[HD];
    sm[i] = n;
    __syncthreads();
    float rot = (i < 64) ? -sm[i + 64] : sm[i - 64];
    buf[idx] = n * cs[(size_t)t * HD + i] + rot * sn[(size_t)t * HD + i];
}

__global__ void __launch_bounds__(256)
silu_mul_kernel(float* __restrict__ g, const float* __restrict__ u, size_t n)
{
    size_t i = (size_t)blockIdx.x * blockDim.x + threadIdx.x;
    size_t stride = (size_t)gridDim.x * blockDim.x;
    for (; i < n; i += stride) {
        float gv = g[i];
        g[i] = gv / (1.f + expf(-gv)) * u[i];
    }
}

extern "C" void kernel_launch(void* const* d_in, const int* in_sizes, int n_in,
                              void* d_out, int out_size)
{
    const float* x    = (const float*)d_in[0];
    const float* cosv = (const float*)d_in[1];
    const float* sinv = (const float*)d_in[2];
    const float* mask = (const float*)d_in[3];
    const float* wq   = (const float*)d_in[4];
    const float* bq   = (const float*)d_in[5];
    const float* wk   = (const float*)d_in[6];
    const float* bk   = (const float*)d_in[7];
    const float* wv   = (const float*)d_in[8];
    const float* bv   = (const float*)d_in[9];
    const float* wo   = (const float*)d_in[10];
    const float* qw   = (const float*)d_in[11];
    const float* kw   = (const float*)d_in[12];
    const float* ln1  = (const float*)d_in[13];
    const float* ln2  = (const float*)d_in[14];
    const float* wg   = (const float*)d_in[15];
    const float* wu   = (const float*)d_in[16];
    const float* wd   = (const float*)d_in[17];
    float* out = (float*)d_out;

    float* s = nullptr;
    cudaGetSymbolAddress((void**)&s, g_scratch);
    float* h      = s + OFF_H;
    float* q      = s + OFF_Q;
    float* kbuf   = s + OFF_K;
    float* vbuf   = s + OFF_V;
    float* scores = s + OFF_SCORES;
    float* attn   = s + OFF_ATTN;
    float* x2     = s + OFF_X2;
    float* gate   = s + OFF_GATE;
    float* up     = s + OFF_UP;

    cudaFuncSetAttribute(cgemm_tn<0>, cudaFuncAttributeMaxDynamicSharedMemorySize, SMEM_TN_BYTES);
    cudaFuncSetAttribute(cgemm_tn<1>, cudaFuncAttributeMaxDynamicSharedMemorySize, SMEM_TN_BYTES);
    cudaFuncSetAttribute(cgemm_tn<2>, cudaFuncAttributeMaxDynamicSharedMemorySize, SMEM_TN_BYTES);
    cudaFuncSetAttribute(cscores,     cudaFuncAttributeMaxDynamicSharedMemorySize, SMEM_TN_BYTES);
    cudaFuncSetAttribute(cpv,         cudaFuncAttributeMaxDynamicSharedMemorySize, SMEM_PV_BYTES);

    // 1. h = rmsnorm(x, ln1)
    rmsnorm_kernel<<<T_TOK, 256>>>(x, ln1, h);

    // 2-4. QKV projections (+bias)
    cgemm_tn<1><<<dim3(HIDN / BN, T_TOK / BM), 256, SMEM_TN_BYTES>>>(h, HIDN, wq, HIDN, q, HIDN, HIDN, bq, nullptr);
    cgemm_tn<1><<<dim3(KVW  / BN, T_TOK / BM), 256, SMEM_TN_BYTES>>>(h, HIDN, wk, HIDN, kbuf, KVW, HIDN, bk, nullptr);
    cgemm_tn<1><<<dim3(KVW  / BN, T_TOK / BM), 256, SMEM_TN_BYTES>>>(h, HIDN, wv, HIDN, vbuf, KVW, HIDN, bv, nullptr);

    // 5-6. per-head RMS + RoPE (in place)
    head_rms_rope_kernel<<<dim3(T_TOK, NH),  HD>>>(q,    qw, cosv, sinv, NH);
    head_rms_rope_kernel<<<dim3(T_TOK, NKV), HD>>>(kbuf, kw, cosv, sinv, NKV);

    // 7. scores (causal blocks only)
    cscores<<<dim3(SEQ / BN, SEQ / BM, BATCH * NH), 256, SMEM_TN_BYTES>>>(q, kbuf, mask, scores);

    // 8. length-aware softmax
    softmax_kernel<<<BATCH * NH * SEQ, 256>>>(scores);

    // 9. attn = P @ V (causal-trimmed K loop)
    cpv<<<dim3(1, SEQ / BM, BATCH * NH), 256, SMEM_PV_BYTES>>>(scores, vbuf, attn);

    // 10. x2 = x + attn @ wo^T
    cgemm_tn<2><<<dim3(HIDN / BN, T_TOK / BM), 256, SMEM_TN_BYTES>>>(attn, HIDN, wo, HIDN, x2, HIDN, HIDN, nullptr, x);

    // 11. h = rmsnorm(x2, ln2)
    rmsnorm_kernel<<<T_TOK, 256>>>(x2, ln2, h);

    // 12-13. gate / up projections
    cgemm_tn<0><<<dim3(FF / BN, T_TOK / BM), 256, SMEM_TN_BYTES>>>(h, HIDN, wg, HIDN, gate, FF, HIDN, nullptr, nullptr);
    cgemm_tn<0><<<dim3(FF / BN, T_TOK / BM), 256, SMEM_TN_BYTES>>>(h, HIDN, wu, HIDN, up, FF, HIDN, nullptr, nullptr);

    // 14. gate = silu(gate) * up
    silu_mul_kernel<<<8192, 256>>>(gate, up, (size_t)T_TOK * FF);

    // 15. out = x2 + gate @ wd^T
    cgemm_tn<2><<<dim3(HIDN / BN, T_TOK / BM), 256, SMEM_TN_BYTES>>>(gate, FF, wd, FF, out, HIDN, FF, nullptr, x2);
}

// round 4
// speedup vs baseline: 1.8992x; 1.8992x over previous
#include <cuda_runtime.h>
#include <mma.h>
#include <math.h>

using namespace nvcuda;

// ---------------- problem constants ----------------
#define T_TOK 4096
#define HIDN  2048
#define NH    16
#define NKV   4
#define HD    128
#define FF    8192
#define BATCH 4
#define SEQ   1024
#define GRP   (NH / NKV)          // 4
#define KVW   (NKV * HD)          // 512
#define EPSV  1e-6f
#define SCALE 0.08838834764831845f  // 1/sqrt(128)

// ---------------- scratch ----------------
#define OFF_H      ((size_t)0)
#define OFF_Q      ((size_t)8388608)
#define OFF_K      ((size_t)16777216)
#define OFF_V      ((size_t)18874368)
#define OFF_SCORES ((size_t)20971520)
#define OFF_ATTN   ((size_t)88080384)
#define OFF_X2     ((size_t)96468992)
#define OFF_GATE   ((size_t)104857600)
#define OFF_UP     ((size_t)138412032)
#define SCRATCH_FLOATS ((size_t)171966464)

__device__ float g_scratch[SCRATCH_FLOATS];

// ---------------- wmma tf32 GEMM config ----------------
#define BM 128
#define BN 128
#define BKT 16
#define APITCH 20
#define BPITCH 20
#define BPITCH_NN 132

__device__ __forceinline__ float tf32r(float x) { return wmma::__float_to_tf32(x); }

// ============================================================
// TN GEMM: C[M,N] = A[M,K] @ B[N,K]^T  (+epilogue)
// EPI: 0 none, 1 +bias[n], 2 +res[m*ldc+n]
// ============================================================
template <int EPI>
__global__ void __launch_bounds__(256, 2)
wgemm_tn(const float* __restrict__ A, int lda,
         const float* __restrict__ B, int ldb,
         float* __restrict__ C, int ldc, int K,
         const float* __restrict__ bias,
         const float* __restrict__ res)
{
    __shared__ __align__(16) float smem[10240];   // 40KB
    float* sA[2] = { smem,        smem + 2560 };
    float* sB[2] = { smem + 5120, smem + 7680 };

    const int tid  = threadIdx.x;
    const int wid  = tid >> 5;
    const int lane = tid & 31;
    const int m0 = blockIdx.y * BM;
    const int n0 = blockIdx.x * BN;
    const int wm = wid & 1;
    const int wn = wid >> 1;

    wmma::fragment<wmma::accumulator, 16, 16, 8, float> c[4][2];
#pragma unroll
    for (int i = 0; i < 4; i++)
#pragma unroll
        for (int j = 0; j < 2; j++) wmma::fill_fragment(c[i][j], 0.f);

    const int lr  = tid >> 2;        // 0..63
    const int lc4 = (tid & 3) << 2;  // 0,4,8,12

    const float* Abase = A + (size_t)(m0 + lr) * lda + lc4;
    const float* Bbase = B + (size_t)(n0 + lr) * ldb + lc4;

    float4 ra0, ra1, rb0, rb1;

    ra0 = *(const float4*)(Abase);
    ra1 = *(const float4*)(Abase + (size_t)64 * lda);
    rb0 = *(const float4*)(Bbase);
    rb1 = *(const float4*)(Bbase + (size_t)64 * ldb);
    {
        float* a = sA[0] + lr * APITCH + lc4;
        a[0] = tf32r(ra0.x); a[1] = tf32r(ra0.y); a[2] = tf32r(ra0.z); a[3] = tf32r(ra0.w);
        float* a2 = sA[0] + (lr + 64) * APITCH + lc4;
        a2[0] = tf32r(ra1.x); a2[1] = tf32r(ra1.y); a2[2] = tf32r(ra1.z); a2[3] = tf32r(ra1.w);
        float* b = sB[0] + lr * BPITCH + lc4;
        b[0] = tf32r(rb0.x); b[1] = tf32r(rb0.y); b[2] = tf32r(rb0.z); b[3] = tf32r(rb0.w);
        float* b2 = sB[0] + (lr + 64) * BPITCH + lc4;
        b2[0] = tf32r(rb1.x); b2[1] = tf32r(rb1.y); b2[2] = tf32r(rb1.z); b2[3] = tf32r(rb1.w);
    }
    __syncthreads();

    const int ntiles = K / BKT;
    for (int t = 0; t < ntiles; t++) {
        const int cur = t & 1;
        if (t + 1 < ntiles) {
            const int k0 = (t + 1) * BKT;
            ra0 = *(const float4*)(Abase + k0);
            ra1 = *(const float4*)(Abase + (size_t)64 * lda + k0);
            rb0 = *(const float4*)(Bbase + k0);
            rb1 = *(const float4*)(Bbase + (size_t)64 * ldb + k0);
        }
#pragma unroll
        for (int ks = 0; ks < BKT; ks += 8) {
            wmma::fragment<wmma::matrix_a, 16, 16, 8, wmma::precision::tf32, wmma::row_major> af[4];
            wmma::fragment<wmma::matrix_b, 16, 16, 8, wmma::precision::tf32, wmma::col_major> bf[2];
#pragma unroll
            for (int i = 0; i < 4; i++)
                wmma::load_matrix_sync(af[i], sA[cur] + (wm * 64 + i * 16) * APITCH + ks, APITCH);
#pragma unroll
            for (int j = 0; j < 2; j++)
                wmma::load_matrix_sync(bf[j], sB[cur] + (wn * 32 + j * 16) * BPITCH + ks, BPITCH);
#pragma unroll
            for (int i = 0; i < 4; i++)
#pragma unroll
                for (int j = 0; j < 2; j++)
                    wmma::mma_sync(c[i][j], af[i], bf[j], c[i][j]);
        }
        if (t + 1 < ntiles) {
            const int nxt = cur ^ 1;
            float* a = sA[nxt] + lr * APITCH + lc4;
            a[0] = tf32r(ra0.x); a[1] = tf32r(ra0.y); a[2] = tf32r(ra0.z); a[3] = tf32r(ra0.w);
            float* a2 = sA[nxt] + (lr + 64) * APITCH + lc4;
            a2[0] = tf32r(ra1.x); a2[1] = tf32r(ra1.y); a2[2] = tf32r(ra1.z); a2[3] = tf32r(ra1.w);
            float* b = sB[nxt] + lr * BPITCH + lc4;
            b[0] = tf32r(rb0.x); b[1] = tf32r(rb0.y); b[2] = tf32r(rb0.z); b[3] = tf32r(rb0.w);
            float* b2 = sB[nxt] + (lr + 64) * BPITCH + lc4;
            b2[0] = tf32r(rb1.x); b2[1] = tf32r(rb1.y); b2[2] = tf32r(rb1.z); b2[3] = tf32r(rb1.w);
        }
        __syncthreads();
    }

    float* stage = smem + wid * 256;
    const int r  = lane >> 1;
    const int cq = (lane & 1) << 3;
#pragma unroll
    for (int i = 0; i < 4; i++) {
#pragma unroll
        for (int j = 0; j < 2; j++) {
            wmma::store_matrix_sync(stage, c[i][j], 16, wmma::mem_row_major);
            __syncwarp();
            const size_t row_g = (size_t)(m0 + wm * 64 + i * 16 + r);
            const size_t col_g = (size_t)(n0 + wn * 32 + j * 16 + cq);
            float4 v0 = *(float4*)&stage[r * 16 + cq];
            float4 v1 = *(float4*)&stage[r * 16 + cq + 4];
            if (EPI == 1) {
                float4 b0 = *(const float4*)&bias[col_g];
                float4 b1 = *(const float4*)&bias[col_g + 4];
                v0.x += b0.x; v0.y += b0.y; v0.z += b0.z; v0.w += b0.w;
                v1.x += b1.x; v1.y += b1.y; v1.z += b1.z; v1.w += b1.w;
            }
            if (EPI == 2) {
                float4 r0 = *(const float4*)&res[row_g * ldc + col_g];
                float4 r1 = *(const float4*)&res[row_g * ldc + col_g + 4];
                v0.x += r0.x; v0.y += r0.y; v0.z += r0.z; v0.w += r0.w;
                v1.x += r1.x; v1.y += r1.y; v1.z += r1.z; v1.w += r1.w;
            }
            *(float4*)&C[row_g * ldc + col_g] = v0;
            *(float4*)&C[row_g * ldc + col_g + 4] = v1;
            __syncwarp();
        }
    }
}

// ============================================================
// Attention scores (causal blocks only, no fill of masked blocks)
// ============================================================
__global__ void __launch_bounds__(256, 2)
wattn_scores(const float* __restrict__ q, const float* __restrict__ k,
             const float* __restrict__ mask, float* __restrict__ scores)
{
    if (blockIdx.x > blockIdx.y) return;  // never read downstream

    const int z = blockIdx.z;
    const int b = z / NH, h = z % NH, kvh = h / GRP;
    const int m0 = blockIdx.y * BM;
    const int n0 = blockIdx.x * BN;
    float* C = scores + (size_t)z * SEQ * SEQ;

    const float* A = q + (size_t)b * SEQ * HIDN + (size_t)h * HD;
    const float* B = k + (size_t)b * SEQ * KVW + (size_t)kvh * HD;
    const float* M = mask + (size_t)b * SEQ * SEQ;

    __shared__ __align__(16) float smem[10240];
    float* sA[2] = { smem,        smem + 2560 };
    float* sB[2] = { smem + 5120, smem + 7680 };

    const int tid  = threadIdx.x;
    const int wid  = tid >> 5;
    const int lane = tid & 31;
    const int wm = wid & 1, wn = wid >> 1;

    wmma::fragment<wmma::accumulator, 16, 16, 8, float> c[4][2];
#pragma unroll
    for (int i = 0; i < 4; i++)
#pragma unroll
        for (int j = 0; j < 2; j++) wmma::fill_fragment(c[i][j], 0.f);

    const int lr  = tid >> 2;
    const int lc4 = (tid & 3) << 2;
    const float* Abase = A + (size_t)(m0 + lr) * HIDN + lc4;
    const float* Bbase = B + (size_t)(n0 + lr) * KVW + lc4;

    float4 ra0, ra1, rb0, rb1;
    ra0 = *(const float4*)(Abase);
    ra1 = *(const float4*)(Abase + (size_t)64 * HIDN);
    rb0 = *(const float4*)(Bbase);
    rb1 = *(const float4*)(Bbase + (size_t)64 * KVW);
    {
        float* a = sA[0] + lr * APITCH + lc4;
        a[0] = tf32r(ra0.x); a[1] = tf32r(ra0.y); a[2] = tf32r(ra0.z); a[3] = tf32r(ra0.w);
        float* a2 = sA[0] + (lr + 64) * APITCH + lc4;
        a2[0] = tf32r(ra1.x); a2[1] = tf32r(ra1.y); a2[2] = tf32r(ra1.z); a2[3] = tf32r(ra1.w);
        float* bp = sB[0] + lr * BPITCH + lc4;
        bp[0] = tf32r(rb0.x); bp[1] = tf32r(rb0.y); bp[2] = tf32r(rb0.z); bp[3] = tf32r(rb0.w);
        float* b2 = sB[0] + (lr + 64) * BPITCH + lc4;
        b2[0] = tf32r(rb1.x); b2[1] = tf32r(rb1.y); b2[2] = tf32r(rb1.z); b2[3] = tf32r(rb1.w);
    }
    __syncthreads();

    const int ntiles = HD / BKT;  // 8
    for (int t = 0; t < ntiles; t++) {
        const int cur = t & 1;
        if (t + 1 < ntiles) {
            const int k0 = (t + 1) * BKT;
            ra0 = *(const float4*)(Abase + k0);
            ra1 = *(const float4*)(Abase + (size_t)64 * HIDN + k0);
            rb0 = *(const float4*)(Bbase + k0);
            rb1 = *(const float4*)(Bbase + (size_t)64 * KVW + k0);
        }
#pragma unroll
        for (int ks = 0; ks < BKT; ks += 8) {
            wmma::fragment<wmma::matrix_a, 16, 16, 8, wmma::precision::tf32, wmma::row_major> af[4];
            wmma::fragment<wmma::matrix_b, 16, 16, 8, wmma::precision::tf32, wmma::col_major> bf[2];
#pragma unroll
            for (int i = 0; i < 4; i++)
                wmma::load_matrix_sync(af[i], sA[cur] + (wm * 64 + i * 16) * APITCH + ks, APITCH);
#pragma unroll
            for (int j = 0; j < 2; j++)
                wmma::load_matrix_sync(bf[j], sB[cur] + (wn * 32 + j * 16) * BPITCH + ks, BPITCH);
#pragma unroll
            for (int i = 0; i < 4; i++)
#pragma unroll
                for (int j = 0; j < 2; j++)
                    wmma::mma_sync(c[i][j], af[i], bf[j], c[i][j]);
        }
        if (t + 1 < ntiles) {
            const int nxt = cur ^ 1;
            float* a = sA[nxt] + lr * APITCH + lc4;
            a[0] = tf32r(ra0.x); a[1] = tf32r(ra0.y); a[2] = tf32r(ra0.z); a[3] = tf32r(ra0.w);
            float* a2 = sA[nxt] + (lr + 64) * APITCH + lc4;
            a2[0] = tf32r(ra1.x); a2[1] = tf32r(ra1.y); a2[2] = tf32r(ra1.z); a2[3] = tf32r(ra1.w);
            float* bp = sB[nxt] + lr * BPITCH + lc4;
            bp[0] = tf32r(rb0.x); bp[1] = tf32r(rb0.y); bp[2] = tf32r(rb0.z); bp[3] = tf32r(rb0.w);
            float* b2 = sB[nxt] + (lr + 64) * BPITCH + lc4;
            b2[0] = tf32r(rb1.x); b2[1] = tf32r(rb1.y); b2[2] = tf32r(rb1.z); b2[3] = tf32r(rb1.w);
        }
        __syncthreads();
    }

    float* stage = smem + wid * 256;
    const int r  = lane >> 1;
    const int cq = (lane & 1) << 3;
#pragma unroll
    for (int i = 0; i < 4; i++) {
#pragma unroll
        for (int j = 0; j < 2; j++) {
            wmma::store_matrix_sync(stage, c[i][j], 16, wmma::mem_row_major);
            __syncwarp();
            const size_t row_g = (size_t)(m0 + wm * 64 + i * 16 + r);
            const size_t col_g = (size_t)(n0 + wn * 32 + j * 16 + cq);
            float4 v0 = *(float4*)&stage[r * 16 + cq];
            float4 v1 = *(float4*)&stage[r * 16 + cq + 4];
            float4 m0v = *(const float4*)&M[row_g * SEQ + col_g];
            float4 m1v = *(const float4*)&M[row_g * SEQ + col_g + 4];
            v0.x = v0.x * SCALE + m0v.x; v0.y = v0.y * SCALE + m0v.y;
            v0.z = v0.z * SCALE + m0v.z; v0.w = v0.w * SCALE + m0v.w;
            v1.x = v1.x * SCALE + m1v.x; v1.y = v1.y * SCALE + m1v.y;
            v1.z = v1.z * SCALE + m1v.z; v1.w = v1.w * SCALE + m1v.w;
            *(float4*)&C[row_g * SEQ + col_g] = v0;
            *(float4*)&C[row_g * SEQ + col_g + 4] = v1;
            __syncwarp();
        }
    }
}

// ============================================================
// PV (NN, causal-trimmed): attn = P @ V, K-loop to m0+128
// ============================================================
__global__ void __launch_bounds__(256, 2)
wattn_pv(const float* __restrict__ p, const float* __restrict__ v,
         float* __restrict__ out)
{
    const int z = blockIdx.z;
    const int b = z / NH, h = z % NH, kvh = h / GRP;
    const float* A = p + (size_t)z * SEQ * SEQ;
    const float* B = v + (size_t)b * SEQ * KVW + (size_t)kvh * HD;
    float* C = out + (size_t)b * SEQ * HIDN + (size_t)h * HD;

    __shared__ __align__(16) float smem[10240];
    float* sA[2] = { smem,        smem + 2560 };
    float* sB[2] = { smem + 5120, smem + 5120 + 2112 };

    const int tid  = threadIdx.x;
    const int wid  = tid >> 5;
    const int lane = tid & 31;
    const int m0 = blockIdx.y * BM;
    const int wm = wid & 1, wn = wid >> 1;

    wmma::fragment<wmma::accumulator, 16, 16, 8, float> c[4][2];
#pragma unroll
    for (int i = 0; i < 4; i++)
#pragma unroll
        for (int j = 0; j < 2; j++) wmma::fill_fragment(c[i][j], 0.f);

    const int lr  = tid >> 2;
    const int lc4 = (tid & 3) << 2;
    const int brr = tid >> 5;
    const int bcc = (tid & 31) << 2;
    const float* Abase = A + (size_t)(m0 + lr) * SEQ + lc4;

    float4 ra0, ra1, rb0, rb1;
    ra0 = *(const float4*)(Abase);
    ra1 = *(const float4*)(Abase + (size_t)64 * SEQ);
    rb0 = *(const float4*)(B + (size_t)brr * KVW + bcc);
    rb1 = *(const float4*)(B + (size_t)(brr + 8) * KVW + bcc);
    {
        float* a = sA[0] + lr * APITCH + lc4;
        a[0] = tf32r(ra0.x); a[1] = tf32r(ra0.y); a[2] = tf32r(ra0.z); a[3] = tf32r(ra0.w);
        float* a2 = sA[0] + (lr + 64) * APITCH + lc4;
        a2[0] = tf32r(ra1.x); a2[1] = tf32r(ra1.y); a2[2] = tf32r(ra1.z); a2[3] = tf32r(ra1.w);
        float* bp = sB[0] + brr * BPITCH_NN + bcc;
        bp[0] = tf32r(rb0.x); bp[1] = tf32r(rb0.y); bp[2] = tf32r(rb0.z); bp[3] = tf32r(rb0.w);
        float* b2 = sB[0] + (brr + 8) * BPITCH_NN + bcc;
        b2[0] = tf32r(rb1.x); b2[1] = tf32r(rb1.y); b2[2] = tf32r(rb1.z); b2[3] = tf32r(rb1.w);
    }
    __syncthreads();

    const int ntiles = (m0 + BM) / BKT;   // causal length
    for (int t = 0; t < ntiles; t++) {
        const int cur = t & 1;
        if (t + 1 < ntiles) {
            const int k0 = (t + 1) * BKT;
            ra0 = *(const float4*)(Abase + k0);
            ra1 = *(const float4*)(Abase + (size_t)64 * SEQ + k0);
            rb0 = *(const float4*)(B + (size_t)(k0 + brr) * KVW + bcc);
            rb1 = *(const float4*)(B + (size_t)(k0 + brr + 8) * KVW + bcc);
        }
#pragma unroll
        for (int ks = 0; ks < BKT; ks += 8) {
            wmma::fragment<wmma::matrix_a, 16, 16, 8, wmma::precision::tf32, wmma::row_major> af[4];
            wmma::fragment<wmma::matrix_b, 16, 16, 8, wmma::precision::tf32, wmma::row_major> bf[2];
#pragma unroll
            for (int i = 0; i < 4; i++)
                wmma::load_matrix_sync(af[i], sA[cur] + (wm * 64 + i * 16) * APITCH + ks, APITCH);
#pragma unroll
            for (int j = 0; j < 2; j++)
                wmma::load_matrix_sync(bf[j], sB[cur] + ks * BPITCH_NN + (wn * 32 + j * 16), BPITCH_NN);
#pragma unroll
            for (int i = 0; i < 4; i++)
#pragma unroll
                for (int j = 0; j < 2; j++)
                    wmma::mma_sync(c[i][j], af[i], bf[j], c[i][j]);
        }
        if (t + 1 < ntiles) {
            const int nxt = cur ^ 1;
            float* a = sA[nxt] + lr * APITCH + lc4;
            a[0] = tf32r(ra0.x); a[1] = tf32r(ra0.y); a[2] = tf32r(ra0.z); a[3] = tf32r(ra0.w);
            float* a2 = sA[nxt] + (lr + 64) * APITCH + lc4;
            a2[0] = tf32r(ra1.x); a2[1] = tf32r(ra1.y); a2[2] = tf32r(ra1.z); a2[3] = tf32r(ra1.w);
            float* bp = sB[nxt] + brr * BPITCH_NN + bcc;
            bp[0] = tf32r(rb0.x); bp[1] = tf32r(rb0.y); bp[2] = tf32r(rb0.z); bp[3] = tf32r(rb0.w);
            float* b2 = sB[nxt] + (brr + 8) * BPITCH_NN + bcc;
            b2[0] = tf32r(rb1.x); b2[1] = tf32r(rb1.y); b2[2] = tf32r(rb1.z); b2[3] = tf32r(rb1.w);
        }
        __syncthreads();
    }

    float* stage = smem + wid * 256;
    const int r  = lane >> 1;
    const int cq = (lane & 1) << 3;
#pragma unroll
    for (int i = 0; i < 4; i++) {
#pragma unroll
        for (int j = 0; j < 2; j++) {
            wmma::store_matrix_sync(stage, c[i][j], 16, wmma::mem_row_major);
            __syncwarp();
            const size_t row_g = (size_t)(m0 + wm * 64 + i * 16 + r);
            const size_t col_g = (size_t)(wn * 32 + j * 16 + cq);
            float4 v0 = *(float4*)&stage[r * 16 + cq];
            float4 v1 = *(float4*)&stage[r * 16 + cq + 4];
            *(float4*)&C[row_g * HIDN + col_g] = v0;
            *(float4*)&C[row_g * HIDN + col_g + 4] = v1;
            __syncwarp();
        }
    }
}

// ---------------- elementwise / reduction kernels ----------------

// length-aware causal softmax: row s normalizes over t < (floor(s/128)+1)*128
__global__ void __launch_bounds__(256)
softmax_kernel(float* __restrict__ s)
{
    const size_t base = (size_t)blockIdx.x * SEQ;
    const int r = blockIdx.x & (SEQ - 1);
    const int L = ((r >> 7) + 1) << 7;
    const int tid = threadIdx.x;
    __shared__ float red[8];

    float vals[4];
    float mx = -1e30f;
    int cnt = 0;
    for (int idx = tid; idx < L; idx += 256) {
        vals[cnt] = s[base + idx];
        mx = fmaxf(mx, vals[cnt]);
        cnt++;
    }
#pragma unroll
    for (int o = 16; o > 0; o >>= 1) mx = fmaxf(mx, __shfl_xor_sync(0xffffffffu, mx, o));
    if ((tid & 31) == 0) red[tid >> 5] = mx;
    __syncthreads();
    float m2 = fmaxf(fmaxf(fmaxf(red[0], red[1]), fmaxf(red[2], red[3])),
                     fmaxf(fmaxf(red[4], red[5]), fmaxf(red[6], red[7])));
    __syncthreads();

    float sum = 0.f;
    for (int c = 0; c < cnt; c++) {
        vals[c] = expf(vals[c] - m2);
        sum += vals[c];
    }
#pragma unroll
    for (int o = 16; o > 0; o >>= 1) sum += __shfl_xor_sync(0xffffffffu, sum, o);
    if ((tid & 31) == 0) red[tid >> 5] = sum;
    __syncthreads();
    float tot = red[0] + red[1] + red[2] + red[3] + red[4] + red[5] + red[6] + red[7];
    float inv = 1.f / tot;
    int c = 0;
    for (int idx = tid; idx < L; idx += 256, c++) s[base + idx] = vals[c] * inv;
}

__global__ void __launch_bounds__(256)
rmsnorm_kernel(const float* __restrict__ x, const float* __restrict__ w,
               float* __restrict__ out)
{
    const size_t base = (size_t)blockIdx.x * HIDN;
    const int tid = threadIdx.x;
    __shared__ float red[8];

    float v[8];
    float ss = 0.f;
#pragma unroll
    for (int j = 0; j < 8; j++) {
        v[j] = x[base + tid + j * 256];
        ss += v[j] * v[j];
    }
#pragma unroll
    for (int o = 16; o > 0; o >>= 1) ss += __shfl_xor_sync(0xffffffffu, ss, o);
    if ((tid & 31) == 0) red[tid >> 5] = ss;
    __syncthreads();
    float tot = red[0] + red[1] + red[2] + red[3] + red[4] + red[5] + red[6] + red[7];
    float r = rsqrtf(tot * (1.f / HIDN) + EPSV);
#pragma unroll
    for (int j = 0; j < 8; j++)
        out[base + tid + j * 256] = v[j] * r * w[tid + j * 256];
}

__global__ void __launch_bounds__(128)
head_rms_rope_kernel(float* __restrict__ buf, const float* __restrict__ w,
                     const float* __restrict__ cs, const float* __restrict__ sn,
                     int nheads)
{
    const int t = blockIdx.x;
    const int h = blockIdx.y;
    const int i = threadIdx.x;
    const size_t idx = (size_t)t * nheads * HD + (size_t)h * HD + i;

    float v = buf[idx];
    float ss = v * v;
#pragma unroll
    for (int o = 16; o > 0; o >>= 1) ss += __shfl_xor_sync(0xffffffffu, ss, o);
    __shared__ float red[4];
    if ((i & 31) == 0) red[i >> 5] = ss;
    __syncthreads();
    float tot = red[0] + red[1] + red[2] + red[3];
    float n = v * rsqrtf(tot * (1.f / HD) + EPSV) * w[i];

    __shared__ float sm[HD];
    sm[i] = n;
    __syncthreads();
    float rot = (i < 64) ? -sm[i + 64] : sm[i - 64];
    buf[idx] = n * cs[(size_t)t * HD + i] + rot * sn[(size_t)t * HD + i];
}

__global__ void __launch_bounds__(256)
silu_mul_kernel(float* __restrict__ g, const float* __restrict__ u, size_t n)
{
    size_t i = (size_t)blockIdx.x * blockDim.x + threadIdx.x;
    size_t stride = (size_t)gridDim.x * blockDim.x;
    for (; i < n; i += stride) {
        float gv = g[i];
        g[i] = gv / (1.f + expf(-gv)) * u[i];
    }
}

extern "C" void kernel_launch(void* const* d_in, const int* in_sizes, int n_in,
                              void* d_out, int out_size)
{
    const float* x    = (const float*)d_in[0];
    const float* cosv = (const float*)d_in[1];
    const float* sinv = (const float*)d_in[2];
    const float* mask = (const float*)d_in[3];
    const float* wq   = (const float*)d_in[4];
    const float* bq   = (const float*)d_in[5];
    const float* wk   = (const float*)d_in[6];
    const float* bk   = (const float*)d_in[7];
    const float* wv   = (const float*)d_in[8];
    const float* bv   = (const float*)d_in[9];
    const float* wo   = (const float*)d_in[10];
    const float* qw   = (const float*)d_in[11];
    const float* kw   = (const float*)d_in[12];
    const float* ln1  = (const float*)d_in[13];
    const float* ln2  = (const float*)d_in[14];
    const float* wg   = (const float*)d_in[15];
    const float* wu   = (const float*)d_in[16];
    const float* wd   = (const float*)d_in[17];
    float* out = (float*)d_out;

    float* s = nullptr;
    cudaGetSymbolAddress((void**)&s, g_scratch);
    float* h      = s + OFF_H;
    float* q      = s + OFF_Q;
    float* kbuf   = s + OFF_K;
    float* vbuf   = s + OFF_V;
    float* scores = s + OFF_SCORES;
    float* attn   = s + OFF_ATTN;
    float* x2     = s + OFF_X2;
    float* gate   = s + OFF_GATE;
    float* up     = s + OFF_UP;

    // 1. h = rmsnorm(x, ln1)
    rmsnorm_kernel<<<T_TOK, 256>>>(x, ln1, h);

    // 2-4. QKV projections (+bias)
    wgemm_tn<1><<<dim3(HIDN / BN, T_TOK / BM), 256>>>(h, HIDN, wq, HIDN, q, HIDN, HIDN, bq, nullptr);
    wgemm_tn<1><<<dim3(KVW  / BN, T_TOK / BM), 256>>>(h, HIDN, wk, HIDN, kbuf, KVW, HIDN, bk, nullptr);
    wgemm_tn<1><<<dim3(KVW  / BN, T_TOK / BM), 256>>>(h, HIDN, wv, HIDN, vbuf, KVW, HIDN, bv, nullptr);

    // 5-6. per-head RMS + RoPE (in place)
    head_rms_rope_kernel<<<dim3(T_TOK, NH),  HD>>>(q,    qw, cosv, sinv, NH);
    head_rms_rope_kernel<<<dim3(T_TOK, NKV), HD>>>(kbuf, kw, cosv, sinv, NKV);

    // 7. scores (lower-triangle blocks only)
    wattn_scores<<<dim3(SEQ / BN, SEQ / BM, BATCH * NH), 256>>>(q, kbuf, mask, scores);

    // 8. length-aware softmax
    softmax_kernel<<<BATCH * NH * SEQ, 256>>>(scores);

    // 9. attn = P @ V (causal-trimmed)
    wattn_pv<<<dim3(1, SEQ / BM, BATCH * NH), 256>>>(scores, vbuf, attn);

    // 10. x2 = x + attn @ wo^T
    wgemm_tn<2><<<dim3(HIDN / BN, T_TOK / BM), 256>>>(attn, HIDN, wo, HIDN, x2, HIDN, HIDN, nullptr, x);

    // 11. h = rmsnorm(x2, ln2)
    rmsnorm_kernel<<<T_TOK, 256>>>(x2, ln2, h);

    // 12-13. gate / up projections
    wgemm_tn<0><<<dim3(FF / BN, T_TOK / BM), 256>>>(h, HIDN, wg, HIDN, gate, FF, HIDN, nullptr, nullptr);
    wgemm_tn<0><<<dim3(FF / BN, T_TOK / BM), 256>>>(h, HIDN, wu, HIDN, up, FF, HIDN, nullptr, nullptr);

    // 14. gate = silu(gate) * up
    silu_mul_kernel<<<8192, 256>>>(gate, up, (size_t)T_TOK * FF);

    // 15. out = x2 + gate @ wd^T
    wgemm_tn<2><<<dim3(HIDN / BN, T_TOK / BM), 256>>>(gate, FF, wd, FF, out, HIDN, FF, nullptr, x2);
}

// round 5
// speedup vs baseline: 4.3615x; 2.2965x over previous
#include <cuda_runtime.h>
#include <cuda_fp16.h>
#include <mma.h>
#include <math.h>
#include <stdint.h>

using namespace nvcuda;

// ---------------- problem constants ----------------
#define T_TOK 4096
#define HIDN  2048
#define NH    16
#define NKV   4
#define HD    128
#define FF    8192
#define BATCH 4
#define SEQ   1024
#define GRP   (NH / NKV)
#define KVW   (NKV * HD)          // 512
#define EPSV  1e-6f
#define SCALE 0.08838834764831845f

// ---------------- fp32 scratch ----------------
#define OFF_Q      ((size_t)0)
#define OFF_K      ((size_t)8388608)
#define OFF_SCORES ((size_t)10485760)
#define OFF_X2     ((size_t)77594624)
#define OFF_GATE   ((size_t)85983232)
#define OFF_UP     ((size_t)119537664)
#define SCRATCH_FLOATS ((size_t)153092096)
__device__ float g_scratch[SCRATCH_FLOATS];

// ---------------- fp16 scratch (halves) ----------------
#define HW_Q     ((size_t)0)
#define HW_K     ((size_t)4194304)
#define HW_V     ((size_t)5242880)
#define HW_O     ((size_t)6291456)
#define HW_G     ((size_t)10485760)
#define HW_U     ((size_t)27262976)
#define HW_D     ((size_t)44040192)
#define H_H16    ((size_t)60817408)
#define H_Q16    ((size_t)69206016)
#define H_K16    ((size_t)77594624)
#define H_V16    ((size_t)79691776)
#define H_P16    ((size_t)81788928)
#define H_ATTN16 ((size_t)148897792)
#define H_GATE16 ((size_t)157286400)
#define HSCRATCH_HALVES ((size_t)190840832)
__device__ __half g_hscratch[HSCRATCH_HALVES];

// ---------------- GEMM config ----------------
#define BM 128
#define BN 128
#define BK 32
#define HPITCH 40                  // 32 + 8 halves
#define HSTAGE (128 * HPITCH)      // 5120 halves
#define HPITCH_B 136               // PV B [BK][BN]
#define HSTAGE_B (BK * HPITCH_B)   // 4352 halves

typedef wmma::fragment<wmma::matrix_a, 16, 16, 16, __half, wmma::row_major> AFragH;
typedef wmma::fragment<wmma::matrix_b, 16, 16, 16, __half, wmma::col_major> BFragHC;
typedef wmma::fragment<wmma::matrix_b, 16, 16, 16, __half, wmma::row_major> BFragHR;
typedef wmma::fragment<wmma::accumulator, 16, 16, 16, float> CFragH;

// ============================================================
// fp16 TN GEMM: C[M,N] = A[M,K] @ B[N,K]^T  (fp32 accum)
// EPI: 0 none, 1 +bias, 2 +res.  HOUT: 0 fp32 C, 1 fp16 C.
// ============================================================
template <int EPI, int HOUT>
__global__ void __launch_bounds__(256, 2)
hgemm_tn(const __half* __restrict__ A, int lda,
         const __half* __restrict__ B, int ldb,
         void* __restrict__ Cv, int ldc, int K,
         const float* __restrict__ bias,
         const float* __restrict__ res)
{
    __shared__ __align__(16) __half smem[4 * HSTAGE];   // 40KB
    __half* sA[2] = { smem,              smem + HSTAGE };
    __half* sB[2] = { smem + 2 * HSTAGE, smem + 3 * HSTAGE };

    const int tid  = threadIdx.x;
    const int wid  = tid >> 5;
    const int lane = tid & 31;
    const int m0 = blockIdx.y * BM;
    const int n0 = blockIdx.x * BN;
    const int wm = wid & 1, wn = wid >> 1;

    CFragH c[4][2];
#pragma unroll
    for (int i = 0; i < 4; i++)
#pragma unroll
        for (int j = 0; j < 2; j++) wmma::fill_fragment(c[i][j], 0.f);

    const int row = tid >> 1;           // 0..127
    const int c0  = (tid & 1) << 4;     // 0 or 16 (halves)
    const __half* gA = A + (size_t)(m0 + row) * lda + c0;
    const __half* gB = B + (size_t)(n0 + row) * ldb + c0;

    uint4 ra0, ra1, rb0, rb1;
    ra0 = *(const uint4*)(gA);
    ra1 = *(const uint4*)(gA + 8);
    rb0 = *(const uint4*)(gB);
    rb1 = *(const uint4*)(gB + 8);
    {
        __half* a = sA[0] + row * HPITCH + c0;
        *(uint4*)a = ra0; *(uint4*)(a + 8) = ra1;
        __half* b = sB[0] + row * HPITCH + c0;
        *(uint4*)b = rb0; *(uint4*)(b + 8) = rb1;
    }
    __syncthreads();

    const int nt = K / BK;
    for (int t = 0; t < nt; t++) {
        const int cur = t & 1;
        if (t + 1 < nt) {
            const int k0 = (t + 1) * BK;
            ra0 = *(const uint4*)(gA + k0);
            ra1 = *(const uint4*)(gA + k0 + 8);
            rb0 = *(const uint4*)(gB + k0);
            rb1 = *(const uint4*)(gB + k0 + 8);
        }
#pragma unroll
        for (int ks = 0; ks < BK; ks += 16) {
            AFragH af[4];
            BFragHC bf[2];
#pragma unroll
            for (int i = 0; i < 4; i++)
                wmma::load_matrix_sync(af[i], sA[cur] + (wm * 64 + i * 16) * HPITCH + ks, HPITCH);
#pragma unroll
            for (int j = 0; j < 2; j++)
                wmma::load_matrix_sync(bf[j], sB[cur] + (wn * 32 + j * 16) * HPITCH + ks, HPITCH);
#pragma unroll
            for (int i = 0; i < 4; i++)
#pragma unroll
                for (int j = 0; j < 2; j++)
                    wmma::mma_sync(c[i][j], af[i], bf[j], c[i][j]);
        }
        if (t + 1 < nt) {
            const int nxt = cur ^ 1;
            __half* a = sA[nxt] + row * HPITCH + c0;
            *(uint4*)a = ra0; *(uint4*)(a + 8) = ra1;
            __half* b = sB[nxt] + row * HPITCH + c0;
            *(uint4*)b = rb0; *(uint4*)(b + 8) = rb1;
        }
        __syncthreads();
    }

    float* stage = reinterpret_cast<float*>(smem) + wid * 256;
    const int r  = lane >> 1;
    const int cq = (lane & 1) << 3;
#pragma unroll
    for (int i = 0; i < 4; i++) {
#pragma unroll
        for (int j = 0; j < 2; j++) {
            wmma::store_matrix_sync(stage, c[i][j], 16, wmma::mem_row_major);
            __syncwarp();
            const size_t row_g = (size_t)(m0 + wm * 64 + i * 16 + r);
            const size_t col_g = (size_t)(n0 + wn * 32 + j * 16 + cq);
            float4 v0 = *(float4*)&stage[r * 16 + cq];
            float4 v1 = *(float4*)&stage[r * 16 + cq + 4];
            if (EPI == 1) {
                float4 b0 = *(const float4*)&bias[col_g];
                float4 b1 = *(const float4*)&bias[col_g + 4];
                v0.x += b0.x; v0.y += b0.y; v0.z += b0.z; v0.w += b0.w;
                v1.x += b1.x; v1.y += b1.y; v1.z += b1.z; v1.w += b1.w;
            }
            if (EPI == 2) {
                float4 r0 = *(const float4*)&res[row_g * ldc + col_g];
                float4 r1 = *(const float4*)&res[row_g * ldc + col_g + 4];
                v0.x += r0.x; v0.y += r0.y; v0.z += r0.z; v0.w += r0.w;
                v1.x += r1.x; v1.y += r1.y; v1.z += r1.z; v1.w += r1.w;
            }
            if (HOUT) {
                __half* C = (__half*)Cv;
                __half2 h[4];
                h[0] = __floats2half2_rn(v0.x, v0.y);
                h[1] = __floats2half2_rn(v0.z, v0.w);
                h[2] = __floats2half2_rn(v1.x, v1.y);
                h[3] = __floats2half2_rn(v1.z, v1.w);
                *(uint4*)&C[row_g * ldc + col_g] = *(uint4*)h;
            } else {
                float* C = (float*)Cv;
                *(float4*)&C[row_g * ldc + col_g] = v0;
                *(float4*)&C[row_g * ldc + col_g + 4] = v1;
            }
            __syncwarp();
        }
    }
}

// ============================================================
// Scores: (q16.k16)*SCALE + mask -> fp32 ; lower-triangle only
// ============================================================
__global__ void __launch_bounds__(256, 2)
hscores(const __half* __restrict__ q, const __half* __restrict__ k,
        const float* __restrict__ mask, float* __restrict__ scores)
{
    if (blockIdx.x > blockIdx.y) return;

    const int z = blockIdx.z;
    const int b = z / NH, h = z % NH, kvh = h / GRP;
    const int m0 = blockIdx.y * BM;
    const int n0 = blockIdx.x * BN;
    const __half* A = q + (size_t)b * SEQ * HIDN + (size_t)h * HD;
    const __half* B = k + (size_t)b * SEQ * KVW + (size_t)kvh * HD;
    const float* M = mask + (size_t)b * SEQ * SEQ;
    float* C = scores + (size_t)z * SEQ * SEQ;

    __shared__ __align__(16) __half smem[4 * HSTAGE];
    __half* sA[2] = { smem,              smem + HSTAGE };
    __half* sB[2] = { smem + 2 * HSTAGE, smem + 3 * HSTAGE };

    const int tid  = threadIdx.x;
    const int wid  = tid >> 5;
    const int lane = tid & 31;
    const int wm = wid & 1, wn = wid >> 1;

    CFragH c[4][2];
#pragma unroll
    for (int i = 0; i < 4; i++)
#pragma unroll
        for (int j = 0; j < 2; j++) wmma::fill_fragment(c[i][j], 0.f);

    const int row = tid >> 1;
    const int c0  = (tid & 1) << 4;
    const __half* gA = A + (size_t)(m0 + row) * HIDN + c0;
    const __half* gB = B + (size_t)(n0 + row) * KVW + c0;

    uint4 ra0, ra1, rb0, rb1;
    ra0 = *(const uint4*)(gA);
    ra1 = *(const uint4*)(gA + 8);
    rb0 = *(const uint4*)(gB);
    rb1 = *(const uint4*)(gB + 8);
    {
        __half* a = sA[0] + row * HPITCH + c0;
        *(uint4*)a = ra0; *(uint4*)(a + 8) = ra1;
        __half* bb = sB[0] + row * HPITCH + c0;
        *(uint4*)bb = rb0; *(uint4*)(bb + 8) = rb1;
    }
    __syncthreads();

    const int nt = HD / BK;   // 4
    for (int t = 0; t < nt; t++) {
        const int cur = t & 1;
        if (t + 1 < nt) {
            const int k0 = (t + 1) * BK;
            ra0 = *(const uint4*)(gA + k0);
            ra1 = *(const uint4*)(gA + k0 + 8);
            rb0 = *(const uint4*)(gB + k0);
            rb1 = *(const uint4*)(gB + k0 + 8);
        }
#pragma unroll
        for (int ks = 0; ks < BK; ks += 16) {
            AFragH af[4];
            BFragHC bf[2];
#pragma unroll
            for (int i = 0; i < 4; i++)
                wmma::load_matrix_sync(af[i], sA[cur] + (wm * 64 + i * 16) * HPITCH + ks, HPITCH);
#pragma unroll
            for (int j = 0; j < 2; j++)
                wmma::load_matrix_sync(bf[j], sB[cur] + (wn * 32 + j * 16) * HPITCH + ks, HPITCH);
#pragma unroll
            for (int i = 0; i < 4; i++)
#pragma unroll
                for (int j = 0; j < 2; j++)
                    wmma::mma_sync(c[i][j], af[i], bf[j], c[i][j]);
        }
        if (t + 1 < nt) {
            const int nxt = cur ^ 1;
            __half* a = sA[nxt] + row * HPITCH + c0;
            *(uint4*)a = ra0; *(uint4*)(a + 8) = ra1;
            __half* bb = sB[nxt] + row * HPITCH + c0;
            *(uint4*)bb = rb0; *(uint4*)(bb + 8) = rb1;
        }
        __syncthreads();
    }

    float* stage = reinterpret_cast<float*>(smem) + wid * 256;
    const int r  = lane >> 1;
    const int cq = (lane & 1) << 3;
#pragma unroll
    for (int i = 0; i < 4; i++) {
#pragma unroll
        for (int j = 0; j < 2; j++) {
            wmma::store_matrix_sync(stage, c[i][j], 16, wmma::mem_row_major);
            __syncwarp();
            const size_t row_g = (size_t)(m0 + wm * 64 + i * 16 + r);
            const size_t col_g = (size_t)(n0 + wn * 32 + j * 16 + cq);
            float4 v0 = *(float4*)&stage[r * 16 + cq];
            float4 v1 = *(float4*)&stage[r * 16 + cq + 4];
            float4 m0v = *(const float4*)&M[row_g * SEQ + col_g];
            float4 m1v = *(const float4*)&M[row_g * SEQ + col_g + 4];
            v0.x = v0.x * SCALE + m0v.x; v0.y = v0.y * SCALE + m0v.y;
            v0.z = v0.z * SCALE + m0v.z; v0.w = v0.w * SCALE + m0v.w;
            v1.x = v1.x * SCALE + m1v.x; v1.y = v1.y * SCALE + m1v.y;
            v1.z = v1.z * SCALE + m1v.z; v1.w = v1.w * SCALE + m1v.w;
            *(float4*)&C[row_g * SEQ + col_g] = v0;
            *(float4*)&C[row_g * SEQ + col_g + 4] = v1;
            __syncwarp();
        }
    }
}

// ============================================================
// PV (NN, causal-trimmed): attn16 = P16 @ V16
// ============================================================
__global__ void __launch_bounds__(256, 2)
hpv(const __half* __restrict__ p, const __half* __restrict__ v,
    __half* __restrict__ out)
{
    const int z = blockIdx.z;
    const int b = z / NH, h = z % NH, kvh = h / GRP;
    const int m0 = blockIdx.y * BM;
    const __half* A = p + (size_t)z * SEQ * SEQ;
    const __half* B = v + (size_t)b * SEQ * KVW + (size_t)kvh * HD;
    __half* C = out + (size_t)b * SEQ * HIDN + (size_t)h * HD;

    __shared__ __align__(16) __half smem[2 * HSTAGE + 2 * HSTAGE_B];
    __half* sA[2] = { smem,              smem + HSTAGE };
    __half* sB[2] = { smem + 2 * HSTAGE, smem + 2 * HSTAGE + HSTAGE_B };

    const int tid  = threadIdx.x;
    const int wid  = tid >> 5;
    const int lane = tid & 31;
    const int wm = wid & 1, wn = wid >> 1;

    CFragH c[4][2];
#pragma unroll
    for (int i = 0; i < 4; i++)
#pragma unroll
        for (int j = 0; j < 2; j++) wmma::fill_fragment(c[i][j], 0.f);

    const int row = tid >> 1;
    const int c0  = (tid & 1) << 4;
    const int br  = tid >> 3;          // 0..31
    const int bc  = (tid & 7) << 4;    // 0..112
    const __half* gA = A + (size_t)(m0 + row) * SEQ + c0;

    uint4 ra0, ra1, rb0, rb1;
    ra0 = *(const uint4*)(gA);
    ra1 = *(const uint4*)(gA + 8);
    rb0 = *(const uint4*)(B + (size_t)br * KVW + bc);
    rb1 = *(const uint4*)(B + (size_t)br * KVW + bc + 8);
    {
        __half* a = sA[0] + row * HPITCH + c0;
        *(uint4*)a = ra0; *(uint4*)(a + 8) = ra1;
        __half* bb = sB[0] + br * HPITCH_B + bc;
        *(uint4*)bb = rb0; *(uint4*)(bb + 8) = rb1;
    }
    __syncthreads();

    const int nt = (m0 + BM) / BK;
    for (int t = 0; t < nt; t++) {
        const int cur = t & 1;
        if (t + 1 < nt) {
            const int k0 = (t + 1) * BK;
            ra0 = *(const uint4*)(gA + k0);
            ra1 = *(const uint4*)(gA + k0 + 8);
            rb0 = *(const uint4*)(B + (size_t)(k0 + br) * KVW + bc);
            rb1 = *(const uint4*)(B + (size_t)(k0 + br) * KVW + bc + 8);
        }
#pragma unroll
        for (int ks = 0; ks < BK; ks += 16) {
            AFragH af[4];
            BFragHR bf[2];
#pragma unroll
            for (int i = 0; i < 4; i++)
                wmma::load_matrix_sync(af[i], sA[cur] + (wm * 64 + i * 16) * HPITCH + ks, HPITCH);
#pragma unroll
            for (int j = 0; j < 2; j++)
                wmma::load_matrix_sync(bf[j], sB[cur] + ks * HPITCH_B + (wn * 32 + j * 16), HPITCH_B);
#pragma unroll
            for (int i = 0; i < 4; i++)
#pragma unroll
                for (int j = 0; j < 2; j++)
                    wmma::mma_sync(c[i][j], af[i], bf[j], c[i][j]);
        }
        if (t + 1 < nt) {
            const int nxt = cur ^ 1;
            __half* a = sA[nxt] + row * HPITCH + c0;
            *(uint4*)a = ra0; *(uint4*)(a + 8) = ra1;
            __half* bb = sB[nxt] + br * HPITCH_B + bc;
            *(uint4*)bb = rb0; *(uint4*)(bb + 8) = rb1;
        }
        __syncthreads();
    }

    float* stage = reinterpret_cast<float*>(smem) + wid * 256;
    const int r  = lane >> 1;
    const int cq = (lane & 1) << 3;
#pragma unroll
    for (int i = 0; i < 4; i++) {
#pragma unroll
        for (int j = 0; j < 2; j++) {
            wmma::store_matrix_sync(stage, c[i][j], 16, wmma::mem_row_major);
            __syncwarp();
            const size_t row_g = (size_t)(m0 + wm * 64 + i * 16 + r);
            const size_t col_g = (size_t)(wn * 32 + j * 16 + cq);
            float4 v0 = *(float4*)&stage[r * 16 + cq];
            float4 v1 = *(float4*)&stage[r * 16 + cq + 4];
            __half2 hh[4];
            hh[0] = __floats2half2_rn(v0.x, v0.y);
            hh[1] = __floats2half2_rn(v0.z, v0.w);
            hh[2] = __floats2half2_rn(v1.x, v1.y);
            hh[3] = __floats2half2_rn(v1.z, v1.w);
            *(uint4*)&C[row_g * HIDN + col_g] = *(uint4*)hh;
            __syncwarp();
        }
    }
}

// ---------------- elementwise / reduction kernels ----------------

__global__ void __launch_bounds__(256)
f2h_kernel(const float* __restrict__ in, __half* __restrict__ out, int n)
{
    int i = (blockIdx.x * blockDim.x + threadIdx.x) * 4;
    int stride = gridDim.x * blockDim.x * 4;
    for (; i < n; i += stride) {
        float4 v = *(const float4*)(in + i);
        __half2 h0 = __floats2half2_rn(v.x, v.y);
        __half2 h1 = __floats2half2_rn(v.z, v.w);
        ((__half2*)(out + i))[0] = h0;
        ((__half2*)(out + i))[1] = h1;
    }
}

// length-aware softmax reading fp32, writing fp16
__global__ void __launch_bounds__(256)
softmax_kernel(const float* __restrict__ s, __half* __restrict__ p16)
{
    const size_t base = (size_t)blockIdx.x * SEQ;
    const int r = blockIdx.x & (SEQ - 1);
    const int L = ((r >> 7) + 1) << 7;
    const int tid = threadIdx.x;
    __shared__ float red[8];

    float vals[4];
    float mx = -1e30f;
    int cnt = 0;
    for (int idx = tid; idx < L; idx += 256) {
        vals[cnt] = s[base + idx];
        mx = fmaxf(mx, vals[cnt]);
        cnt++;
    }
#pragma unroll
    for (int o = 16; o > 0; o >>= 1) mx = fmaxf(mx, __shfl_xor_sync(0xffffffffu, mx, o));
    if ((tid & 31) == 0) red[tid >> 5] = mx;
    __syncthreads();
    float m2 = fmaxf(fmaxf(fmaxf(red[0], red[1]), fmaxf(red[2], red[3])),
                     fmaxf(fmaxf(red[4], red[5]), fmaxf(red[6], red[7])));
    __syncthreads();

    float sum = 0.f;
    for (int c = 0; c < cnt; c++) {
        vals[c] = expf(vals[c] - m2);
        sum += vals[c];
    }
#pragma unroll
    for (int o = 16; o > 0; o >>= 1) sum += __shfl_xor_sync(0xffffffffu, sum, o);
    if ((tid & 31) == 0) red[tid >> 5] = sum;
    __syncthreads();
    float tot = red[0] + red[1] + red[2] + red[3] + red[4] + red[5] + red[6] + red[7];
    float inv = 1.f / tot;
    int c = 0;
    for (int idx = tid; idx < L; idx += 256, c++)
        p16[base + idx] = __float2half_rn(vals[c] * inv);
}

// RMSNorm -> fp16 output
__global__ void __launch_bounds__(256)
rmsnorm_h_kernel(const float* __restrict__ x, const float* __restrict__ w,
                 __half* __restrict__ out)
{
    const size_t base = (size_t)blockIdx.x * HIDN;
    const int tid = threadIdx.x;
    __shared__ float red[8];

    float v[8];
    float ss = 0.f;
#pragma unroll
    for (int j = 0; j < 8; j++) {
        v[j] = x[base + tid + j * 256];
        ss += v[j] * v[j];
    }
#pragma unroll
    for (int o = 16; o > 0; o >>= 1) ss += __shfl_xor_sync(0xffffffffu, ss, o);
    if ((tid & 31) == 0) red[tid >> 5] = ss;
    __syncthreads();
    float tot = red[0] + red[1] + red[2] + red[3] + red[4] + red[5] + red[6] + red[7];
    float r = rsqrtf(tot * (1.f / HIDN) + EPSV);
#pragma unroll
    for (int j = 0; j < 8; j++)
        out[base + tid + j * 256] = __float2half_rn(v[j] * r * w[tid + j * 256]);
}

// per-head RMS + RoPE: fp32 in, fp16 out
__global__ void __launch_bounds__(128)
head_rms_rope_kernel(const float* __restrict__ buf, const float* __restrict__ w,
                     const float* __restrict__ cs, const float* __restrict__ sn,
                     __half* __restrict__ out16, int nheads)
{
    const int t = blockIdx.x;
    const int h = blockIdx.y;
    const int i = threadIdx.x;
    const size_t idx = (size_t)t * nheads * HD + (size_t)h * HD + i;

    float v = buf[idx];
    float ss = v * v;
#pragma unroll
    for (int o = 16; o > 0; o >>= 1) ss += __shfl_xor_sync(0xffffffffu, ss, o);
    __shared__ float red[4];
    if ((i & 31) == 0) red[i >> 5] = ss;
    __syncthreads();
    float tot = red[0] + red[1] + red[2] + red[3];
    float n = v * rsqrtf(tot * (1.f / HD) + EPSV) * w[i];

    __shared__ float sm[HD];
    sm[i] = n;
    __syncthreads();
    float rot = (i < 64) ? -sm[i + 64] : sm[i - 64];
    out16[idx] = __float2half_rn(n * cs[(size_t)t * HD + i] + rot * sn[(size_t)t * HD + i]);
}

// silu(g)*u -> fp16
__global__ void __launch_bounds__(256)
silu_mul_h_kernel(const float* __restrict__ g, const float* __restrict__ u,
                  __half* __restrict__ out, size_t n)
{
    size_t i = (size_t)blockIdx.x * blockDim.x + threadIdx.x;
    size_t stride = (size_t)gridDim.x * blockDim.x;
    for (; i < n; i += stride) {
        float gv = g[i];
        out[i] = __float2half_rn(gv / (1.f + expf(-gv)) * u[i]);
    }
}

extern "C" void kernel_launch(void* const* d_in, const int* in_sizes, int n_in,
                              void* d_out, int out_size)
{
    const float* x    = (const float*)d_in[0];
    const float* cosv = (const float*)d_in[1];
    const float* sinv = (const float*)d_in[2];
    const float* mask = (const float*)d_in[3];
    const float* wq   = (const float*)d_in[4];
    const float* bq   = (const float*)d_in[5];
    const float* wk   = (const float*)d_in[6];
    const float* bk   = (const float*)d_in[7];
    const float* wv   = (const float*)d_in[8];
    const float* bv   = (const float*)d_in[9];
    const float* wo   = (const float*)d_in[10];
    const float* qw   = (const float*)d_in[11];
    const float* kw   = (const float*)d_in[12];
    const float* ln1  = (const float*)d_in[13];
    const float* ln2  = (const float*)d_in[14];
    const float* wg   = (const float*)d_in[15];
    const float* wu   = (const float*)d_in[16];
    const float* wd   = (const float*)d_in[17];
    float* out = (float*)d_out;

    float* s = nullptr;
    cudaGetSymbolAddress((void**)&s, g_scratch);
    __half* hs = nullptr;
    cudaGetSymbolAddress((void**)&hs, g_hscratch);

    float* q      = s + OFF_Q;
    float* kbuf   = s + OFF_K;
    float* scores = s + OFF_SCORES;
    float* x2     = s + OFF_X2;
    float* gate   = s + OFF_GATE;
    float* up     = s + OFF_UP;

    __half* hwq   = hs + HW_Q;
    __half* hwk   = hs + HW_K;
    __half* hwv   = hs + HW_V;
    __half* hwo   = hs + HW_O;
    __half* hwg   = hs + HW_G;
    __half* hwu   = hs + HW_U;
    __half* hwd   = hs + HW_D;
    __half* h16   = hs + H_H16;
    __half* q16   = hs + H_Q16;
    __half* k16   = hs + H_K16;
    __half* v16   = hs + H_V16;
    __half* p16   = hs + H_P16;
    __half* at16  = hs + H_ATTN16;
    __half* g16   = hs + H_GATE16;

    // 0. weight fp32 -> fp16
    f2h_kernel<<<2048, 256>>>(wq, hwq, HIDN * HIDN);
    f2h_kernel<<<1024, 256>>>(wk, hwk, KVW * HIDN);
    f2h_kernel<<<1024, 256>>>(wv, hwv, KVW * HIDN);
    f2h_kernel<<<2048, 256>>>(wo, hwo, HIDN * HIDN);
    f2h_kernel<<<4096, 256>>>(wg, hwg, FF * HIDN);
    f2h_kernel<<<4096, 256>>>(wu, hwu, FF * HIDN);
    f2h_kernel<<<4096, 256>>>(wd, hwd, HIDN * FF);

    // 1. h16 = rmsnorm(x, ln1) in fp16
    rmsnorm_h_kernel<<<T_TOK, 256>>>(x, ln1, h16);

    // 2-4. QKV projections (+bias)
    hgemm_tn<1, 0><<<dim3(HIDN / BN, T_TOK / BM), 256>>>(h16, HIDN, hwq, HIDN, q, HIDN, HIDN, bq, nullptr);
    hgemm_tn<1, 0><<<dim3(KVW  / BN, T_TOK / BM), 256>>>(h16, HIDN, hwk, HIDN, kbuf, KVW, HIDN, bk, nullptr);
    hgemm_tn<1, 1><<<dim3(KVW  / BN, T_TOK / BM), 256>>>(h16, HIDN, hwv, HIDN, v16, KVW, HIDN, bv, nullptr);

    // 5-6. per-head RMS + RoPE -> fp16
    head_rms_rope_kernel<<<dim3(T_TOK, NH),  HD>>>(q,    qw, cosv, sinv, q16, NH);
    head_rms_rope_kernel<<<dim3(T_TOK, NKV), HD>>>(kbuf, kw, cosv, sinv, k16, NKV);

    // 7. scores (lower triangle)
    hscores<<<dim3(SEQ / BN, SEQ / BM, BATCH * NH), 256>>>(q16, k16, mask, scores);

    // 8. softmax -> p16
    softmax_kernel<<<BATCH * NH * SEQ, 256>>>(scores, p16);

    // 9. attn16 = P @ V (causal-trimmed)
    hpv<<<dim3(1, SEQ / BM, BATCH * NH), 256>>>(p16, v16, at16);

    // 10. x2 = x + attn @ wo^T
    hgemm_tn<2, 0><<<dim3(HIDN / BN, T_TOK / BM), 256>>>(at16, HIDN, hwo, HIDN, x2, HIDN, HIDN, nullptr, x);

    // 11. h16 = rmsnorm(x2, ln2)
    rmsnorm_h_kernel<<<T_TOK, 256>>>(x2, ln2, h16);

    // 12-13. gate / up projections
    hgemm_tn<0, 0><<<dim3(FF / BN, T_TOK / BM), 256>>>(h16, HIDN, hwg, HIDN, gate, FF, HIDN, nullptr, nullptr);
    hgemm_tn<0, 0><<<dim3(FF / BN, T_TOK / BM), 256>>>(h16, HIDN, hwu, HIDN, up, FF, HIDN, nullptr, nullptr);

    // 14. g16 = silu(gate) * up
    silu_mul_h_kernel<<<8192, 256>>>(gate, up, g16, (size_t)T_TOK * FF);

    // 15. out = x2 + g16 @ wd^T
    hgemm_tn<2, 0><<<dim3(HIDN / BN, T_TOK / BM), 256>>>(g16, FF, hwd, FF, out, HIDN, FF, nullptr, x2);
}